// round 12
// baseline (speedup 1.0000x reference)
#include <cuda_runtime.h>
#include <cuda_bf16.h>
#include <cstdint>
#include <cstddef>

#define NN 32768
#define EE 524288
#define HH 128
#define GG 64
#define NG 512   // nodes per graph

// ---------------- device scratch (static, no allocations) ----------------
__device__ int      g_ei64;
__device__ int      g_cnt[NN];
__device__ int      g_off[NN + 1];
__device__ int      g_cur[NN];
__device__ int      g_bsum[128];
__device__ int      g_boff[128];
__device__ int      g_srcs[EE];
__device__ float    g_dinv[NN];
__device__ float4   g_hs[NN * 32];                 // fp32 messages; later reused for V
__device__ uint32_t g_h_hi[NN * 64];               // h split-bf16 (2 elems per uint32)
__device__ uint32_t g_h_lo[NN * 64];
__device__ uint32_t g_q_hi[NN * 64];               // also holds split x before QKV
__device__ uint32_t g_q_lo[NN * 64];
__device__ uint32_t g_k_hi[NN * 64];
__device__ uint32_t g_k_lo[NN * 64];
__device__ uint32_t g_wt_hi[5 * 128 * 64];         // 5 weights, transposed [n][k] split-bf16
__device__ uint32_t g_wt_lo[5 * 128 * 64];
__device__ float    g_scores[(size_t)GG * NG * NG]; // 64 MB scaled scores
__device__ float    g_rowm[GG * NG];
__device__ float    g_rowz[GG * NG];
__device__ float    g_w[GG * NG];

// ---------------- mma.sync / ldmatrix / cp.async helpers ----------------
#define MMA_BF16(D, a0, a1, a2, a3, b0, b1)                                   \
    asm volatile(                                                             \
        "mma.sync.aligned.m16n8k16.row.col.f32.bf16.bf16.f32 "                \
        "{%0,%1,%2,%3}, {%4,%5,%6,%7}, {%8,%9}, {%0,%1,%2,%3};"               \
        : "+f"((D)[0]), "+f"((D)[1]), "+f"((D)[2]), "+f"((D)[3])              \
        : "r"(a0), "r"(a1), "r"(a2), "r"(a3), "r"(b0), "r"(b1))

#define LDSM4(r0, r1, r2, r3, addr)                                           \
    asm volatile("ldmatrix.sync.aligned.m8n8.x4.shared.b16 {%0,%1,%2,%3}, [%4];" \
                 : "=r"(r0), "=r"(r1), "=r"(r2), "=r"(r3) : "r"(addr))

#define LDSM2(r0, r1, addr)                                                   \
    asm volatile("ldmatrix.sync.aligned.m8n8.x2.shared.b16 {%0,%1}, [%2];"    \
                 : "=r"(r0), "=r"(r1) : "r"(addr))

__device__ __forceinline__ void cp16(uint32_t dst, const void* src) {
    asm volatile("cp.async.ca.shared.global [%0], [%1], 16;" :: "r"(dst), "l"(src));
}
#define CP_COMMIT() asm volatile("cp.async.commit_group;" ::: "memory")
#define CP_WAIT(n)  asm volatile("cp.async.wait_group %0;" :: "n"(n) : "memory")

#define PADB 80                  // 32 bf16 per row padded to 80 B
#define A_TILE (64 * PADB)       // 5120 B  (64-row A tile)
#define B_TILE (128 * PADB)      // 10240 B (128-row B tile)
#define STAGE_B (2 * A_TILE + 2 * B_TILE)  // 30720 B
#define DSMEM (2 * STAGE_B)      // 61440 B dynamic smem

__device__ __forceinline__ uint32_t pack_hi(float a, float b) {
    __nv_bfloat162 h = __halves2bfloat162(__float2bfloat16(a), __float2bfloat16(b));
    return *(uint32_t*)&h;
}
__device__ __forceinline__ uint32_t pack_lo(float a, float b) {
    __nv_bfloat16 ha = __float2bfloat16(a), hb = __float2bfloat16(b);
    __nv_bfloat162 l = __floats2bfloat162_rn(a - __bfloat162float(ha),
                                             b - __bfloat162float(hb));
    return *(uint32_t*)&l;
}

// ---------------- edge index accessors ----------------
__device__ __forceinline__ int edge_src(const void* ei, int e) {
    int v = g_ei64 ? (int)((const long long*)ei)[e] : ((const int*)ei)[e];
    return v & (NN - 1);
}
__device__ __forceinline__ int edge_dst(const void* ei, int e) {
    int v = g_ei64 ? (int)((const long long*)ei)[EE + e] : ((const int*)ei)[EE + e];
    return v & (NN - 1);
}

__global__ void __launch_bounds__(256) k_dtype_zero(const void* ei) {
    int i = blockIdx.x * 256 + threadIdx.x;
    g_cnt[i] = 0;
    if (blockIdx.x == 0) {
        __shared__ int s_ok;
        if (threadIdx.x == 0) s_ok = 1;
        __syncthreads();
        const long long* p = (const long long*)ei;
        int bad = 0;
#pragma unroll
        for (int k = 0; k < 4; k++) {
            long long v = p[threadIdx.x * 4 + k];
            if (v < 0 || v >= NN) bad = 1;
        }
        if (bad) atomicExch(&s_ok, 0);
        __syncthreads();
        if (threadIdx.x == 0) g_ei64 = s_ok;
    }
}

__global__ void k_hist(const void* __restrict__ ei) {
    int e = blockIdx.x * blockDim.x + threadIdx.x;
    if (e < EE) atomicAdd(&g_cnt[edge_dst(ei, e)], 1);
}
__global__ void __launch_bounds__(256) k_scan1() {
    __shared__ int sh[256];
    int t = threadIdx.x;
    int i = blockIdx.x * 256 + t;
    int c = g_cnt[i];
    sh[t] = c;
    __syncthreads();
#pragma unroll
    for (int o = 1; o < 256; o <<= 1) {
        int v = (t >= o) ? sh[t - o] : 0;
        __syncthreads();
        sh[t] += v;
        __syncthreads();
    }
    g_off[i] = sh[t] - c;
    if (t == 255) g_bsum[blockIdx.x] = sh[255];
}
__global__ void __launch_bounds__(128) k_scan2() {
    __shared__ int sh[128];
    int t = threadIdx.x;
    int c = g_bsum[t];
    sh[t] = c;
    __syncthreads();
#pragma unroll
    for (int o = 1; o < 128; o <<= 1) {
        int v = (t >= o) ? sh[t - o] : 0;
        __syncthreads();
        sh[t] += v;
        __syncthreads();
    }
    g_boff[t] = sh[t] - c;
}
__global__ void __launch_bounds__(256) k_scan3() {
    int i = blockIdx.x * 256 + threadIdx.x;
    int off = g_off[i] + g_boff[i >> 8];
    g_off[i] = off;
    g_cur[i] = off;
    g_dinv[i] = rsqrtf((float)g_cnt[i] + 1.0f);
    if (i == 0) g_off[NN] = EE;
}
__global__ void k_fill(const void* __restrict__ ei) {
    int e = blockIdx.x * blockDim.x + threadIdx.x;
    if (e >= EE) return;
    int s = edge_src(ei, e);
    int d = edge_dst(ei, e);
    int slot = atomicAdd(&g_cur[d], 1);
    g_srcs[slot] = s;
}

// ---------------- pre-split: x -> g_q (split), weights -> g_wt transposed split ----------------
__global__ void __launch_bounds__(256) k_split(const float* __restrict__ x,
                                               const float* __restrict__ W1,
                                               const float* __restrict__ W2,
                                               const float* __restrict__ Wq,
                                               const float* __restrict__ Wk,
                                               const float* __restrict__ Wv) {
    int bx = blockIdx.x, tid = threadIdx.x;
    if (bx < 256) {
        size_t m0 = (size_t)bx * 128;
        const float4* X4 = (const float4*)(x + m0 * 128);
#pragma unroll
        for (int it = 0; it < 16; it++) {
            int idx = it * 256 + tid;
            int row = idx >> 5, c4 = idx & 31;
            float4 v = X4[idx];
            size_t o = (m0 + row) * 64 + c4 * 2;
            g_q_hi[o]     = pack_hi(v.x, v.y);
            g_q_hi[o + 1] = pack_hi(v.z, v.w);
            g_q_lo[o]     = pack_lo(v.x, v.y);
            g_q_lo[o + 1] = pack_lo(v.z, v.w);
        }
    } else {
        int w = bx - 256;  // 0..4
        const float* W = (w == 0) ? W1 : (w == 1) ? W2 : (w == 2) ? Wq : (w == 3) ? Wk : Wv;
        const float4* W4 = (const float4*)W;
        uint32_t* Hi = g_wt_hi + w * 8192;
        uint32_t* Lo = g_wt_lo + w * 8192;
#pragma unroll
        for (int it = 0; it < 8; it++) {
            int item = it * 256 + tid;
            int k2 = item >> 5, n4 = item & 31;
            float4 va = W4[(2 * k2) * 32 + n4];
            float4 vb = W4[(2 * k2 + 1) * 32 + n4];
            float aa[4] = {va.x, va.y, va.z, va.w};
            float bb[4] = {vb.x, vb.y, vb.z, vb.w};
#pragma unroll
            for (int j = 0; j < 4; j++) {
                int n = n4 * 4 + j;
                Hi[n * 64 + k2] = pack_hi(aa[j], bb[j]);
                Lo[n * 64 + k2] = pack_lo(aa[j], bb[j]);
            }
        }
    }
}

// ---------------- GEMM core: 64x128 tile, ldmatrix + split-3 MMA over one 32-K chunk ----------------
__device__ __forceinline__ void mma_chunk(float d[2][4][4], uint32_t base,
                                          int wm, int wn, int lane) {
    uint32_t aHi = base, aLo = base + A_TILE;
    uint32_t bHi = base + 2 * A_TILE, bLo = base + 2 * A_TILE + B_TILE;
    uint32_t aOff = (uint32_t)((wm * 32 + (lane & 15)) * PADB + (lane >> 4) * 16);
    uint32_t bOff = (uint32_t)((wn * 32 + (lane & 7)) * PADB + ((lane >> 3) & 1) * 16);
#pragma unroll
    for (int ks = 0; ks < 2; ks++) {
        uint32_t bh[4][2], bl[4][2];
#pragma unroll
        for (int nt = 0; nt < 4; nt++) {
            LDSM2(bh[nt][0], bh[nt][1], bHi + bOff + nt * 8 * PADB + ks * 32);
            LDSM2(bl[nt][0], bl[nt][1], bLo + bOff + nt * 8 * PADB + ks * 32);
        }
#pragma unroll
        for (int mt = 0; mt < 2; mt++) {
            uint32_t ah0, ah1, ah2, ah3, al0, al1, al2, al3;
            LDSM4(ah0, ah1, ah2, ah3, aHi + aOff + mt * 16 * PADB + ks * 32);
            LDSM4(al0, al1, al2, al3, aLo + aOff + mt * 16 * PADB + ks * 32);
#pragma unroll
            for (int nt = 0; nt < 4; nt++) {
                MMA_BF16(d[mt][nt], ah0, ah1, ah2, ah3, bh[nt][0], bh[nt][1]);
                MMA_BF16(d[mt][nt], ah0, ah1, ah2, ah3, bl[nt][0], bl[nt][1]);
                MMA_BF16(d[mt][nt], al0, al1, al2, al3, bh[nt][0], bh[nt][1]);
            }
        }
    }
}

// load one 32-K chunk: A 64 rows (hi/lo), B 128 rows (hi/lo); rows are 16 uint4 wide
__device__ __forceinline__ void load_chunk(uint32_t base,
                                           const uint4* Ah, const uint4* Al, size_t aRow0,
                                           const uint4* Bh, const uint4* Bl, size_t bRow0,
                                           int kc, int tid) {
    {
        int row = tid >> 2, q = tid & 3;
        uint32_t doff = (uint32_t)(row * PADB + q * 16);
        size_t ga = (aRow0 + row) * 16 + kc * 4 + q;
        cp16(base + doff,          Ah + ga);
        cp16(base + A_TILE + doff, Al + ga);
    }
#pragma unroll
    for (int it = 0; it < 2; it++) {
        int idx = it * 256 + tid;
        int row = idx >> 2, q = idx & 3;
        uint32_t doff = (uint32_t)(row * PADB + q * 16);
        size_t gb = (bRow0 + row) * 16 + kc * 4 + q;
        cp16(base + 2 * A_TILE + doff,          Bh + gb);
        cp16(base + 2 * A_TILE + B_TILE + doff, Bl + gb);
    }
}

// epilogue: fp32 -> g_hs (dstMode 0), split-bf16 -> q (1) / k (2)
__device__ __forceinline__ void gemm_epilogue(float d[2][4][4], const float* bias,
                                              int dstMode, size_t m0,
                                              int wm, int wn, int gid, int tig) {
    float* C = (float*)g_hs;
    uint32_t* Hq = (dstMode == 1) ? g_q_hi : g_k_hi;
    uint32_t* Lq = (dstMode == 1) ? g_q_lo : g_k_lo;
#pragma unroll
    for (int mt = 0; mt < 2; mt++) {
        size_t row0 = m0 + wm * 32 + mt * 16 + gid;
        size_t row1 = row0 + 8;
#pragma unroll
        for (int nt = 0; nt < 4; nt++) {
            int col = wn * 32 + nt * 8 + tig * 2;
            float bx = 0.f, by = 0.f;
            if (bias) { bx = bias[col]; by = bias[col + 1]; }
            float v00 = d[mt][nt][0] + bx, v01 = d[mt][nt][1] + by;
            float v10 = d[mt][nt][2] + bx, v11 = d[mt][nt][3] + by;
            if (dstMode == 0) {
                *(float2*)(C + row0 * 128 + col) = make_float2(v00, v01);
                *(float2*)(C + row1 * 128 + col) = make_float2(v10, v11);
            } else {
                int ci = col >> 1;
                Hq[row0 * 64 + ci] = pack_hi(v00, v01);
                Lq[row0 * 64 + ci] = pack_lo(v00, v01);
                Hq[row1 * 64 + ci] = pack_hi(v10, v11);
                Lq[row1 * 64 + ci] = pack_lo(v10, v11);
            }
        }
    }
}

// ---------------- unified node GEMM: C[64-tile,128] = A @ W ----------------
__global__ void __launch_bounds__(256, 3) k_tgemm(const float* __restrict__ bias0,
                                                  const float* __restrict__ bias1,
                                                  const float* __restrict__ bias2,
                                                  int mode) {
    extern __shared__ __align__(16) uint8_t dsm[];
    int tid = threadIdx.x, wid = tid >> 5, lane = tid & 31;
    int gid = lane >> 2, tig = lane & 3;
    int wm = wid >> 2, wn = wid & 3;
    size_t m0 = (size_t)blockIdx.x * 64;

    const uint32_t *srcHi, *srcLo;
    int widx, dstMode;
    const float* bias = nullptr;
    if (mode == 0)      { srcHi = g_q_hi; srcLo = g_q_lo; widx = 0; dstMode = 0; }
    else if (mode == 1) { srcHi = g_h_hi; srcLo = g_h_lo; widx = 1; dstMode = 0; }
    else {
        int y = blockIdx.y;
        srcHi = g_h_hi; srcLo = g_h_lo; widx = 2 + y;
        dstMode = (y == 0) ? 1 : (y == 1) ? 2 : 0;
        bias = (y == 0) ? bias0 : (y == 1) ? bias1 : bias2;
    }
    const uint4* Ah = (const uint4*)srcHi;
    const uint4* Al = (const uint4*)srcLo;
    const uint4* Bh = (const uint4*)(g_wt_hi + widx * 8192);
    const uint4* Bl = (const uint4*)(g_wt_lo + widx * 8192);
    uint32_t smBase = (uint32_t)__cvta_generic_to_shared(dsm);

    float d[2][4][4];
#pragma unroll
    for (int mt = 0; mt < 2; mt++)
#pragma unroll
        for (int nt = 0; nt < 4; nt++)
#pragma unroll
            for (int c = 0; c < 4; c++) d[mt][nt][c] = 0.f;

    load_chunk(smBase, Ah, Al, m0, Bh, Bl, 0, 0, tid);
    CP_COMMIT();
#pragma unroll
    for (int kc = 0; kc < 4; kc++) {
        CP_WAIT(0);
        __syncthreads();
        if (kc < 3) {
            load_chunk(smBase + ((kc + 1) & 1) * STAGE_B, Ah, Al, m0, Bh, Bl, 0, kc + 1, tid);
            CP_COMMIT();
        }
        mma_chunk(d, smBase + (kc & 1) * STAGE_B, wm, wn, lane);
    }
    gemm_epilogue(d, bias, dstMode, m0, wm, wn, gid, tig);
}

// ---------------- scores + rowstats fused ----------------
// grid (NG/64, GG): CTA computes 64 rows x all 512 cols (4 K-tiles via flat 16-chunk
// pipeline), writes scaled scores, then computes per-row max / 1/Z from warm L2.
#define SCALE 0.08838834764831845f

__global__ void __launch_bounds__(256, 3) k_tscores() {
    extern __shared__ __align__(16) uint8_t dsm[];
    int tid = threadIdx.x, wid = tid >> 5, lane = tid & 31;
    int gid = lane >> 2, tig = lane & 3;
    int wm = wid >> 2, wn = wid & 3;
    int ti = blockIdx.x, g = blockIdx.y;

    size_t qrow = (size_t)(g * NG + ti * 64);
    const uint4* Qh = (const uint4*)g_q_hi;
    const uint4* Ql = (const uint4*)g_q_lo;
    const uint4* Kh = (const uint4*)g_k_hi;
    const uint4* Kl = (const uint4*)g_k_lo;
    uint32_t smBase = (uint32_t)__cvta_generic_to_shared(dsm);
    float* Sg = g_scores + (size_t)g * NG * NG;

    float d[2][4][4];
#pragma unroll
    for (int mt = 0; mt < 2; mt++)
#pragma unroll
        for (int nt = 0; nt < 4; nt++)
#pragma unroll
            for (int c = 0; c < 4; c++) d[mt][nt][c] = 0.f;

    load_chunk(smBase, Qh, Ql, qrow, Kh, Kl, (size_t)(g * NG), 0, tid);
    CP_COMMIT();
    for (int c = 0; c < 16; c++) {
        CP_WAIT(0);
        __syncthreads();
        if (c < 15) {
            int nc = c + 1;
            size_t krow = (size_t)(g * NG + (nc >> 2) * 128);
            load_chunk(smBase + (nc & 1) * STAGE_B, Qh, Ql, qrow, Kh, Kl, krow, nc & 3, tid);
            CP_COMMIT();
        }
        mma_chunk(d, smBase + (c & 1) * STAGE_B, wm, wn, lane);
        if ((c & 3) == 3) {
            int tj = c >> 2;
#pragma unroll
            for (int mt = 0; mt < 2; mt++) {
                int i0 = ti * 64 + wm * 32 + mt * 16 + gid;
                int i1 = i0 + 8;
#pragma unroll
                for (int nt = 0; nt < 4; nt++) {
                    int col = tj * 128 + wn * 32 + nt * 8 + tig * 2;
                    *(float2*)(Sg + (size_t)i0 * NG + col) =
                        make_float2(d[mt][nt][0] * SCALE, d[mt][nt][1] * SCALE);
                    *(float2*)(Sg + (size_t)i1 * NG + col) =
                        make_float2(d[mt][nt][2] * SCALE, d[mt][nt][3] * SCALE);
                    d[mt][nt][0] = d[mt][nt][1] = d[mt][nt][2] = d[mt][nt][3] = 0.f;
                }
            }
        }
    }

    // stats phase: 8 warps x 8 rows (L2-warm reads of our own tile)
    __syncthreads();
#pragma unroll
    for (int r8 = 0; r8 < 8; r8++) {
        int row = g * NG + ti * 64 + wid * 8 + r8;
        const float* r = g_scores + (size_t)row * NG;
        float v[16];
        float m = -1e30f;
#pragma unroll
        for (int i = 0; i < 16; i++) { v[i] = r[lane + i * 32]; m = fmaxf(m, v[i]); }
#pragma unroll
        for (int o = 16; o > 0; o >>= 1) m = fmaxf(m, __shfl_xor_sync(0xffffffffu, m, o));
        float z = 0.f;
#pragma unroll
        for (int i = 0; i < 16; i++) z += __expf(v[i] - m);
#pragma unroll
        for (int o = 16; o > 0; o >>= 1) z += __shfl_xor_sync(0xffffffffu, z, o);
        if (lane == 0) { g_rowm[row] = m; g_rowz[row] = 1.0f / z; }
    }
}

// ---------------- aggregate (writes h as split-bf16); 4-wide MLP gather ----------------
__global__ void __launch_bounds__(256) k_aggregate(const float* __restrict__ b) {
    int t = blockIdx.x * blockDim.x + threadIdx.x;
    int i = t >> 5;
    if (i >= NN) return;
    int lane = t & 31;

    float di = g_dinv[i];
    float4 self = g_hs[(size_t)i * 32 + lane];
    float4 acc;
    acc.x = di * self.x; acc.y = di * self.y;
    acc.z = di * self.z; acc.w = di * self.w;

    int j = g_off[i];
    int end = g_off[i + 1];
    for (; j + 3 < end; j += 4) {
        int s0 = g_srcs[j], s1 = g_srcs[j + 1], s2 = g_srcs[j + 2], s3 = g_srcs[j + 3];
        float w0 = g_dinv[s0], w1 = g_dinv[s1], w2 = g_dinv[s2], w3 = g_dinv[s3];
        float4 v0 = g_hs[(size_t)s0 * 32 + lane];
        float4 v1 = g_hs[(size_t)s1 * 32 + lane];
        float4 v2 = g_hs[(size_t)s2 * 32 + lane];
        float4 v3 = g_hs[(size_t)s3 * 32 + lane];
        acc.x += w0 * v0.x + w1 * v1.x + w2 * v2.x + w3 * v3.x;
        acc.y += w0 * v0.y + w1 * v1.y + w2 * v2.y + w3 * v3.y;
        acc.z += w0 * v0.z + w1 * v1.z + w2 * v2.z + w3 * v3.z;
        acc.w += w0 * v0.w + w1 * v1.w + w2 * v2.w + w3 * v3.w;
    }
    for (; j < end; j++) {
        int s0 = g_srcs[j];
        float w0 = g_dinv[s0];
        float4 v0 = g_hs[(size_t)s0 * 32 + lane];
        acc.x += w0 * v0.x; acc.y += w0 * v0.y;
        acc.z += w0 * v0.z; acc.w += w0 * v0.w;
    }
    float4 bb = ((const float4*)b)[lane];
    float o0 = fmaxf(acc.x * di + bb.x, 0.f);
    float o1 = fmaxf(acc.y * di + bb.y, 0.f);
    float o2 = fmaxf(acc.z * di + bb.z, 0.f);
    float o3 = fmaxf(acc.w * di + bb.w, 0.f);
    size_t base = (size_t)i * 64 + lane * 2;
    g_h_hi[base]     = pack_hi(o0, o1);
    g_h_hi[base + 1] = pack_hi(o2, o3);
    g_h_lo[base]     = pack_lo(o0, o1);
    g_h_lo[base + 1] = pack_lo(o2, o3);
}

// ---------------- column weights: direct write, no atomics ----------------
// grid (GG, 4): CTA covers 128 columns of one graph over all 512 rows
__global__ void __launch_bounds__(128) k_colsum() {
    __shared__ float sm_m[NG];
    __shared__ float sm_zi[NG];
    int g = blockIdx.x, jt = blockIdx.y, tid = threadIdx.x;
    for (int i = tid; i < NG; i += 128) {
        sm_m[i]  = g_rowm[g * NG + i];
        sm_zi[i] = g_rowz[g * NG + i];
    }
    __syncthreads();
    int j = jt * 128 + tid;
    const float* Sg = g_scores + (size_t)g * NG * NG;
    float w = 0.f;
#pragma unroll 4
    for (int i = 0; i < NG; i++)
        w += __expf(Sg[(size_t)i * NG + j] - sm_m[i]) * sm_zi[i];
    g_w[g * NG + j] = w;
}

// ---------------- pooled + MLP head ----------------
__global__ void __launch_bounds__(128) k_pooled_head(const float* __restrict__ Wh1,
                                                     const float* __restrict__ bh1,
                                                     const float* __restrict__ Wh2,
                                                     const float* __restrict__ bh2,
                                                     float* __restrict__ out) {
    int g = blockIdx.x, d = threadIdx.x;
    __shared__ float ws[NG];
    __shared__ float pooled[HH];
    __shared__ float hid[64];
    for (int i = d; i < NG; i += 128) ws[i] = g_w[g * NG + i];
    __syncthreads();
    const float* vg = (const float*)g_hs + (size_t)g * NG * HH;
    float acc = 0.f;
    for (int j = 0; j < NG; j++) acc += ws[j] * vg[j * HH + d];
    pooled[d] = acc * (1.0f / (float)NG);
    __syncthreads();
    if (d < 64) {
        float h = bh1[d];
#pragma unroll 8
        for (int k = 0; k < HH; k++) h += pooled[k] * Wh1[k * 64 + d];
        hid[d] = fmaxf(h, 0.f);
    }
    __syncthreads();
    if (d == 0) {
        float o = bh2[0];
#pragma unroll 8
        for (int h = 0; h < 64; h++) o += hid[h] * Wh2[h];
        out[g] = o;
    }
}

// ---------------- launch ----------------
extern "C" void kernel_launch(void* const* d_in, const int* in_sizes, int n_in,
                              void* d_out, int out_size) {
    const float* x   = (const float*)d_in[0];
    const void*  ei  = d_in[1];
    const float* W1  = (const float*)d_in[3];
    const float* b1  = (const float*)d_in[4];
    const float* W2  = (const float*)d_in[5];
    const float* b2  = (const float*)d_in[6];
    const float* Wq  = (const float*)d_in[7];
    const float* bq  = (const float*)d_in[8];
    const float* Wk  = (const float*)d_in[9];
    const float* bk  = (const float*)d_in[10];
    const float* Wv  = (const float*)d_in[11];
    const float* bv  = (const float*)d_in[12];
    const float* Wh1 = (const float*)d_in[13];
    const float* bh1 = (const float*)d_in[14];
    const float* Wh2 = (const float*)d_in[15];
    const float* bh2 = (const float*)d_in[16];
    float* out = (float*)d_out;

    cudaFuncSetAttribute(k_tgemm,   cudaFuncAttributeMaxDynamicSharedMemorySize, DSMEM);
    cudaFuncSetAttribute(k_tscores, cudaFuncAttributeMaxDynamicSharedMemorySize, DSMEM);

    k_dtype_zero<<<NN / 256, 256>>>(ei);                     // #1
    k_hist<<<EE / 256, 256>>>(ei);                           // #2
    k_split<<<261, 256>>>(x, W1, W2, Wq, Wk, Wv);            // #3
    k_tgemm<<<NN / 64, 256, DSMEM>>>(nullptr, nullptr, nullptr, 0);  // #4 conv1 (profiled)
    k_scan1<<<NN / 256, 256>>>();                            // #5
    k_scan2<<<1, 128>>>();                                   // #6
    k_scan3<<<NN / 256, 256>>>();                            // #7
    k_fill<<<EE / 256, 256>>>(ei);                           // #8

    k_aggregate<<<NN * 32 / 256, 256>>>(b1);
    k_tgemm<<<NN / 64, 256, DSMEM>>>(nullptr, nullptr, nullptr, 1);  // conv2
    k_aggregate<<<NN * 32 / 256, 256>>>(b2);

    dim3 qkv(NN / 64, 3);
    k_tgemm<<<qkv, 256, DSMEM>>>(bq, bk, bv, 2);             // fused QKV

    dim3 sg(NG / 64, GG);                                    // (8, 64)
    k_tscores<<<sg, 256, DSMEM>>>();                         // scores + rowstats
    dim3 cs(GG, NG / 128);                                   // (64, 4)
    k_colsum<<<cs, 128>>>();
    k_pooled_head<<<GG, HH>>>(Wh1, bh1, Wh2, bh2, out);
}

// round 13
// speedup vs baseline: 1.1371x; 1.1371x over previous
#include <cuda_runtime.h>
#include <cuda_bf16.h>
#include <cstdint>
#include <cstddef>

#define NN 32768
#define EE 524288
#define HH 128
#define GG 64
#define NG 512   // nodes per graph

// ---------------- device scratch (static, no allocations) ----------------
__device__ int      g_ei64;
__device__ int      g_cnt[NN];
__device__ int      g_off[NN + 1];
__device__ int      g_cur[NN];
__device__ int      g_bsum[128];
__device__ int      g_boff[128];
__device__ int      g_srcs[EE];
__device__ float    g_dinv[NN];
__device__ float4   g_hs[NN * 32];                 // fp32 messages; later reused for V
__device__ uint32_t g_h_hi[NN * 64];               // h split-bf16 (2 elems per uint32)
__device__ uint32_t g_h_lo[NN * 64];
__device__ uint32_t g_q_hi[NN * 64];               // also holds split x before QKV
__device__ uint32_t g_q_lo[NN * 64];
__device__ uint32_t g_k_hi[NN * 64];
__device__ uint32_t g_k_lo[NN * 64];
__device__ uint32_t g_wt_hi[5 * 128 * 64];         // 5 weights, transposed [n][k] split-bf16
__device__ uint32_t g_wt_lo[5 * 128 * 64];
__device__ float    g_scores[(size_t)GG * NG * NG]; // 64 MB scaled scores
__device__ float    g_rowm[GG * NG];
__device__ float    g_rowz[GG * NG];
__device__ float    g_w[GG * NG];

// ---------------- mma.sync / ldmatrix / cp.async helpers ----------------
#define MMA_BF16(D, a0, a1, a2, a3, b0, b1)                                   \
    asm volatile(                                                             \
        "mma.sync.aligned.m16n8k16.row.col.f32.bf16.bf16.f32 "                \
        "{%0,%1,%2,%3}, {%4,%5,%6,%7}, {%8,%9}, {%0,%1,%2,%3};"               \
        : "+f"((D)[0]), "+f"((D)[1]), "+f"((D)[2]), "+f"((D)[3])              \
        : "r"(a0), "r"(a1), "r"(a2), "r"(a3), "r"(b0), "r"(b1))

#define LDSM4(r0, r1, r2, r3, addr)                                           \
    asm volatile("ldmatrix.sync.aligned.m8n8.x4.shared.b16 {%0,%1,%2,%3}, [%4];" \
                 : "=r"(r0), "=r"(r1), "=r"(r2), "=r"(r3) : "r"(addr))

#define LDSM2(r0, r1, addr)                                                   \
    asm volatile("ldmatrix.sync.aligned.m8n8.x2.shared.b16 {%0,%1}, [%2];"    \
                 : "=r"(r0), "=r"(r1) : "r"(addr))

__device__ __forceinline__ void cp16(uint32_t dst, const void* src) {
    asm volatile("cp.async.ca.shared.global [%0], [%1], 16;" :: "r"(dst), "l"(src));
}
#define CP_COMMIT() asm volatile("cp.async.commit_group;" ::: "memory")
#define CP_WAIT(n)  asm volatile("cp.async.wait_group %0;" :: "n"(n) : "memory")

#define PADB 80            // 32 bf16 per row padded to 80 B (bank-disjoint ldmatrix)
#define TILE_B (128 * PADB)     // 10240 B per tile
#define STAGE_B (4 * TILE_B)    // 40960 B per pipeline stage
#define DSMEM (2 * STAGE_B)     // 81920 B dynamic smem

__device__ __forceinline__ uint32_t pack_hi(float a, float b) {
    __nv_bfloat162 h = __halves2bfloat162(__float2bfloat16(a), __float2bfloat16(b));
    return *(uint32_t*)&h;
}
__device__ __forceinline__ uint32_t pack_lo(float a, float b) {
    __nv_bfloat16 ha = __float2bfloat16(a), hb = __float2bfloat16(b);
    __nv_bfloat162 l = __floats2bfloat162_rn(a - __bfloat162float(ha),
                                             b - __bfloat162float(hb));
    return *(uint32_t*)&l;
}

// ---------------- edge index accessors ----------------
__device__ __forceinline__ int edge_src(const void* ei, int e) {
    int v = g_ei64 ? (int)((const long long*)ei)[e] : ((const int*)ei)[e];
    return v & (NN - 1);
}
__device__ __forceinline__ int edge_dst(const void* ei, int e) {
    int v = g_ei64 ? (int)((const long long*)ei)[EE + e] : ((const int*)ei)[EE + e];
    return v & (NN - 1);
}

__global__ void __launch_bounds__(256) k_dtype_zero(const void* ei) {
    int i = blockIdx.x * 256 + threadIdx.x;
    g_cnt[i] = 0;
    if (blockIdx.x == 0) {
        __shared__ int s_ok;
        if (threadIdx.x == 0) s_ok = 1;
        __syncthreads();
        const long long* p = (const long long*)ei;
        int bad = 0;
#pragma unroll
        for (int k = 0; k < 4; k++) {
            long long v = p[threadIdx.x * 4 + k];
            if (v < 0 || v >= NN) bad = 1;
        }
        if (bad) atomicExch(&s_ok, 0);
        __syncthreads();
        if (threadIdx.x == 0) g_ei64 = s_ok;
    }
}

__global__ void k_hist(const void* __restrict__ ei) {
    int e = blockIdx.x * blockDim.x + threadIdx.x;
    if (e < EE) atomicAdd(&g_cnt[edge_dst(ei, e)], 1);
}
__global__ void __launch_bounds__(256) k_scan1() {
    __shared__ int sh[256];
    int t = threadIdx.x;
    int i = blockIdx.x * 256 + t;
    int c = g_cnt[i];
    sh[t] = c;
    __syncthreads();
#pragma unroll
    for (int o = 1; o < 256; o <<= 1) {
        int v = (t >= o) ? sh[t - o] : 0;
        __syncthreads();
        sh[t] += v;
        __syncthreads();
    }
    g_off[i] = sh[t] - c;
    if (t == 255) g_bsum[blockIdx.x] = sh[255];
}
__global__ void __launch_bounds__(128) k_scan2() {
    __shared__ int sh[128];
    int t = threadIdx.x;
    int c = g_bsum[t];
    sh[t] = c;
    __syncthreads();
#pragma unroll
    for (int o = 1; o < 128; o <<= 1) {
        int v = (t >= o) ? sh[t - o] : 0;
        __syncthreads();
        sh[t] += v;
        __syncthreads();
    }
    g_boff[t] = sh[t] - c;
}
__global__ void __launch_bounds__(256) k_scan3() {
    int i = blockIdx.x * 256 + threadIdx.x;
    int off = g_off[i] + g_boff[i >> 8];
    g_off[i] = off;
    g_cur[i] = off;
    g_dinv[i] = rsqrtf((float)g_cnt[i] + 1.0f);
    if (i == 0) g_off[NN] = EE;
}
__global__ void k_fill(const void* __restrict__ ei) {
    int e = blockIdx.x * blockDim.x + threadIdx.x;
    if (e >= EE) return;
    int s = edge_src(ei, e);
    int d = edge_dst(ei, e);
    int slot = atomicAdd(&g_cur[d], 1);
    g_srcs[slot] = s;
}

// ---------------- pre-split: x -> g_q (split), weights -> g_wt transposed split ----------------
__global__ void __launch_bounds__(256) k_split(const float* __restrict__ x,
                                               const float* __restrict__ W1,
                                               const float* __restrict__ W2,
                                               const float* __restrict__ Wq,
                                               const float* __restrict__ Wk,
                                               const float* __restrict__ Wv) {
    int bx = blockIdx.x, tid = threadIdx.x;
    if (bx < 256) {
        size_t m0 = (size_t)bx * 128;
        const float4* X4 = (const float4*)(x + m0 * 128);
#pragma unroll
        for (int it = 0; it < 16; it++) {
            int idx = it * 256 + tid;
            int row = idx >> 5, c4 = idx & 31;
            float4 v = X4[idx];
            size_t o = (m0 + row) * 64 + c4 * 2;
            g_q_hi[o]     = pack_hi(v.x, v.y);
            g_q_hi[o + 1] = pack_hi(v.z, v.w);
            g_q_lo[o]     = pack_lo(v.x, v.y);
            g_q_lo[o + 1] = pack_lo(v.z, v.w);
        }
    } else {
        int w = bx - 256;  // 0..4
        const float* W = (w == 0) ? W1 : (w == 1) ? W2 : (w == 2) ? Wq : (w == 3) ? Wk : Wv;
        const float4* W4 = (const float4*)W;
        uint32_t* Hi = g_wt_hi + w * 8192;
        uint32_t* Lo = g_wt_lo + w * 8192;
#pragma unroll
        for (int it = 0; it < 8; it++) {
            int item = it * 256 + tid;
            int k2 = item >> 5, n4 = item & 31;
            float4 va = W4[(2 * k2) * 32 + n4];
            float4 vb = W4[(2 * k2 + 1) * 32 + n4];
            float aa[4] = {va.x, va.y, va.z, va.w};
            float bb[4] = {vb.x, vb.y, vb.z, vb.w};
#pragma unroll
            for (int j = 0; j < 4; j++) {
                int n = n4 * 4 + j;
                Hi[n * 64 + k2] = pack_hi(aa[j], bb[j]);
                Lo[n * 64 + k2] = pack_lo(aa[j], bb[j]);
            }
        }
    }
}

// ---------------- GEMM core: 128x128 tile, ldmatrix + split-3 MMA over one 32-K chunk ----------------
__device__ __forceinline__ void mma_chunk(float d[4][4][4], uint32_t base,
                                          int wm, int wn, int lane) {
    uint32_t aHi = base, aLo = base + TILE_B;
    uint32_t bHi = base + 2 * TILE_B, bLo = base + 3 * TILE_B;
    uint32_t aOff = (uint32_t)((wm * 64 + (lane & 15)) * PADB + (lane >> 4) * 16);
    uint32_t bOff = (uint32_t)((wn * 32 + (lane & 7)) * PADB + ((lane >> 3) & 1) * 16);
#pragma unroll
    for (int ks = 0; ks < 2; ks++) {
        uint32_t bh[4][2], bl[4][2];
#pragma unroll
        for (int nt = 0; nt < 4; nt++) {
            LDSM2(bh[nt][0], bh[nt][1], bHi + bOff + nt * 8 * PADB + ks * 32);
            LDSM2(bl[nt][0], bl[nt][1], bLo + bOff + nt * 8 * PADB + ks * 32);
        }
#pragma unroll
        for (int mt = 0; mt < 4; mt++) {
            uint32_t ah0, ah1, ah2, ah3, al0, al1, al2, al3;
            LDSM4(ah0, ah1, ah2, ah3, aHi + aOff + mt * 16 * PADB + ks * 32);
            LDSM4(al0, al1, al2, al3, aLo + aOff + mt * 16 * PADB + ks * 32);
#pragma unroll
            for (int nt = 0; nt < 4; nt++) {
                MMA_BF16(d[mt][nt], ah0, ah1, ah2, ah3, bh[nt][0], bh[nt][1]);
                MMA_BF16(d[mt][nt], ah0, ah1, ah2, ah3, bl[nt][0], bl[nt][1]);
                MMA_BF16(d[mt][nt], al0, al1, al2, al3, bh[nt][0], bh[nt][1]);
            }
        }
    }
}

// load one 32-K chunk (4 x 128-row tiles) via cp.async; global rows are 16 uint4 wide
__device__ __forceinline__ void load_chunk(uint32_t base,
                                           const uint4* Ah, const uint4* Al, size_t aRow0,
                                           const uint4* Bh, const uint4* Bl, size_t bRow0,
                                           int kc, int tid) {
#pragma unroll
    for (int it = 0; it < 2; it++) {
        int idx = it * 256 + tid;
        int row = idx >> 2, q = idx & 3;
        uint32_t doff = (uint32_t)(row * PADB + q * 16);
        size_t ga = (aRow0 + row) * 16 + kc * 4 + q;
        size_t gb = (bRow0 + row) * 16 + kc * 4 + q;
        cp16(base + doff,              Ah + ga);
        cp16(base + TILE_B + doff,     Al + ga);
        cp16(base + 2 * TILE_B + doff, Bh + gb);
        cp16(base + 3 * TILE_B + doff, Bl + gb);
    }
}

// epilogue: fp32 -> g_hs (dstMode 0), split-bf16 -> q (1) / k (2)
__device__ __forceinline__ void gemm_epilogue(float d[4][4][4], const float* bias,
                                              int dstMode, size_t m0,
                                              int wm, int wn, int gid, int tig) {
    float* C = (float*)g_hs;
    uint32_t* Hq = (dstMode == 1) ? g_q_hi : g_k_hi;
    uint32_t* Lq = (dstMode == 1) ? g_q_lo : g_k_lo;
#pragma unroll
    for (int mt = 0; mt < 4; mt++) {
        size_t row0 = m0 + wm * 64 + mt * 16 + gid;
        size_t row1 = row0 + 8;
#pragma unroll
        for (int nt = 0; nt < 4; nt++) {
            int col = wn * 32 + nt * 8 + tig * 2;
            float bx = 0.f, by = 0.f;
            if (bias) { bx = bias[col]; by = bias[col + 1]; }
            float v00 = d[mt][nt][0] + bx, v01 = d[mt][nt][1] + by;
            float v10 = d[mt][nt][2] + bx, v11 = d[mt][nt][3] + by;
            if (dstMode == 0) {
                *(float2*)(C + row0 * 128 + col) = make_float2(v00, v01);
                *(float2*)(C + row1 * 128 + col) = make_float2(v10, v11);
            } else {
                int ci = col >> 1;
                Hq[row0 * 64 + ci] = pack_hi(v00, v01);
                Lq[row0 * 64 + ci] = pack_lo(v00, v01);
                Hq[row1 * 64 + ci] = pack_hi(v10, v11);
                Lq[row1 * 64 + ci] = pack_lo(v10, v11);
            }
        }
    }
}

// ---------------- unified node GEMM: C[128-tile,128] = A @ W ----------------
// mode 0: conv1 (A = split x in g_q, W#0, dst g_hs)
// mode 1: conv2 (A = g_h, W#1, dst g_hs)
// mode 2: QKV   (A = g_h, W#(2+y), dst q/k/hs by blockIdx.y)
__global__ void __launch_bounds__(256, 2) k_tgemm(const float* __restrict__ bias0,
                                                  const float* __restrict__ bias1,
                                                  const float* __restrict__ bias2,
                                                  int mode) {
    extern __shared__ __align__(16) uint8_t dsm[];
    int tid = threadIdx.x, wid = tid >> 5, lane = tid & 31;
    int gid = lane >> 2, tig = lane & 3;
    int wm = wid >> 2, wn = wid & 3;
    size_t m0 = (size_t)blockIdx.x * 128;

    const uint32_t *srcHi, *srcLo;
    int widx, dstMode;
    const float* bias = nullptr;
    if (mode == 0)      { srcHi = g_q_hi; srcLo = g_q_lo; widx = 0; dstMode = 0; }
    else if (mode == 1) { srcHi = g_h_hi; srcLo = g_h_lo; widx = 1; dstMode = 0; }
    else {
        int y = blockIdx.y;
        srcHi = g_h_hi; srcLo = g_h_lo; widx = 2 + y;
        dstMode = (y == 0) ? 1 : (y == 1) ? 2 : 0;
        bias = (y == 0) ? bias0 : (y == 1) ? bias1 : bias2;
    }
    const uint4* Ah = (const uint4*)srcHi;
    const uint4* Al = (const uint4*)srcLo;
    const uint4* Bh = (const uint4*)(g_wt_hi + widx * 8192);
    const uint4* Bl = (const uint4*)(g_wt_lo + widx * 8192);
    uint32_t smBase = (uint32_t)__cvta_generic_to_shared(dsm);

    float d[4][4][4];
#pragma unroll
    for (int mt = 0; mt < 4; mt++)
#pragma unroll
        for (int nt = 0; nt < 4; nt++)
#pragma unroll
            for (int c = 0; c < 4; c++) d[mt][nt][c] = 0.f;

    load_chunk(smBase, Ah, Al, m0, Bh, Bl, 0, 0, tid);
    CP_COMMIT();
    for (int kc = 0; kc < 4; kc++) {
        if (kc < 3) {
            load_chunk(smBase + ((kc + 1) & 1) * STAGE_B, Ah, Al, m0, Bh, Bl, 0, kc + 1, tid);
            CP_COMMIT();
            CP_WAIT(1);
        } else {
            CP_WAIT(0);
        }
        __syncthreads();
        mma_chunk(d, smBase + (kc & 1) * STAGE_B, wm, wn, lane);
        __syncthreads();
    }
    gemm_epilogue(d, bias, dstMode, m0, wm, wn, gid, tig);
}

// ---------------- scores: S-tile = Q @ K^T * SCALE ----------------
#define SCALE 0.08838834764831845f

__global__ void __launch_bounds__(256, 2) k_tscores() {
    extern __shared__ __align__(16) uint8_t dsm[];
    int tid = threadIdx.x, wid = tid >> 5, lane = tid & 31;
    int gid = lane >> 2, tig = lane & 3;
    int wm = wid >> 2, wn = wid & 3;
    int g = blockIdx.z, ti = blockIdx.y, tj = blockIdx.x;

    size_t qrow = (size_t)(g * NG + ti * 128);
    size_t krow = (size_t)(g * NG + tj * 128);
    const uint4* Qh = (const uint4*)g_q_hi;
    const uint4* Ql = (const uint4*)g_q_lo;
    const uint4* Kh = (const uint4*)g_k_hi;
    const uint4* Kl = (const uint4*)g_k_lo;
    uint32_t smBase = (uint32_t)__cvta_generic_to_shared(dsm);

    float d[4][4][4];
#pragma unroll
    for (int mt = 0; mt < 4; mt++)
#pragma unroll
        for (int nt = 0; nt < 4; nt++)
#pragma unroll
            for (int c = 0; c < 4; c++) d[mt][nt][c] = 0.f;

    load_chunk(smBase, Qh, Ql, qrow, Kh, Kl, krow, 0, tid);
    CP_COMMIT();
    for (int kc = 0; kc < 4; kc++) {
        if (kc < 3) {
            load_chunk(smBase + ((kc + 1) & 1) * STAGE_B, Qh, Ql, qrow, Kh, Kl, krow, kc + 1, tid);
            CP_COMMIT();
            CP_WAIT(1);
        } else {
            CP_WAIT(0);
        }
        __syncthreads();
        mma_chunk(d, smBase + (kc & 1) * STAGE_B, wm, wn, lane);
        __syncthreads();
    }

    float* Sg = g_scores + (size_t)g * NG * NG;
#pragma unroll
    for (int mt = 0; mt < 4; mt++) {
        int i0 = ti * 128 + wm * 64 + mt * 16 + gid;
        int i1 = i0 + 8;
#pragma unroll
        for (int nt = 0; nt < 4; nt++) {
            int col = tj * 128 + wn * 32 + nt * 8 + tig * 2;
            *(float2*)(Sg + (size_t)i0 * NG + col) =
                make_float2(d[mt][nt][0] * SCALE, d[mt][nt][1] * SCALE);
            *(float2*)(Sg + (size_t)i1 * NG + col) =
                make_float2(d[mt][nt][2] * SCALE, d[mt][nt][3] * SCALE);
        }
    }
}

// ---------------- aggregate (writes h as split-bf16); 4-wide MLP gather ----------------
__global__ void __launch_bounds__(256) k_aggregate(const float* __restrict__ b) {
    int t = blockIdx.x * blockDim.x + threadIdx.x;
    int i = t >> 5;
    if (i >= NN) return;
    int lane = t & 31;

    float di = g_dinv[i];
    float4 self = g_hs[(size_t)i * 32 + lane];
    float4 acc;
    acc.x = di * self.x; acc.y = di * self.y;
    acc.z = di * self.z; acc.w = di * self.w;

    int j = g_off[i];
    int end = g_off[i + 1];
    for (; j + 3 < end; j += 4) {
        int s0 = g_srcs[j], s1 = g_srcs[j + 1], s2 = g_srcs[j + 2], s3 = g_srcs[j + 3];
        float w0 = g_dinv[s0], w1 = g_dinv[s1], w2 = g_dinv[s2], w3 = g_dinv[s3];
        float4 v0 = g_hs[(size_t)s0 * 32 + lane];
        float4 v1 = g_hs[(size_t)s1 * 32 + lane];
        float4 v2 = g_hs[(size_t)s2 * 32 + lane];
        float4 v3 = g_hs[(size_t)s3 * 32 + lane];
        acc.x += w0 * v0.x + w1 * v1.x + w2 * v2.x + w3 * v3.x;
        acc.y += w0 * v0.y + w1 * v1.y + w2 * v2.y + w3 * v3.y;
        acc.z += w0 * v0.z + w1 * v1.z + w2 * v2.z + w3 * v3.z;
        acc.w += w0 * v0.w + w1 * v1.w + w2 * v2.w + w3 * v3.w;
    }
    for (; j < end; j++) {
        int s0 = g_srcs[j];
        float w0 = g_dinv[s0];
        float4 v0 = g_hs[(size_t)s0 * 32 + lane];
        acc.x += w0 * v0.x; acc.y += w0 * v0.y;
        acc.z += w0 * v0.z; acc.w += w0 * v0.w;
    }
    float4 bb = ((const float4*)b)[lane];
    float o0 = fmaxf(acc.x * di + bb.x, 0.f);
    float o1 = fmaxf(acc.y * di + bb.y, 0.f);
    float o2 = fmaxf(acc.z * di + bb.z, 0.f);
    float o3 = fmaxf(acc.w * di + bb.w, 0.f);
    size_t base = (size_t)i * 64 + lane * 2;
    g_h_hi[base]     = pack_hi(o0, o1);
    g_h_hi[base + 1] = pack_hi(o2, o3);
    g_h_lo[base]     = pack_lo(o0, o1);
    g_h_lo[base + 1] = pack_lo(o2, o3);
}

// ---------------- per-row softmax stats ----------------
__global__ void k_rowstats() {
    int gt = blockIdx.x * blockDim.x + threadIdx.x;
    int row = gt >> 5, lane = gt & 31;
    if (row >= GG * NG) return;
    const float* r = g_scores + (size_t)row * NG;
    float v[16];
    float m = -1e30f;
#pragma unroll
    for (int i = 0; i < 16; i++) { v[i] = r[lane + i * 32]; m = fmaxf(m, v[i]); }
#pragma unroll
    for (int o = 16; o > 0; o >>= 1) m = fmaxf(m, __shfl_xor_sync(0xffffffffu, m, o));
    float z = 0.f;
#pragma unroll
    for (int i = 0; i < 16; i++) z += __expf(v[i] - m);
#pragma unroll
    for (int o = 16; o > 0; o >>= 1) z += __shfl_xor_sync(0xffffffffu, z, o);
    if (lane == 0) { g_rowm[row] = m; g_rowz[row] = 1.0f / z; }
}

// ---------------- column weights: direct write, no atomics ----------------
// grid (GG, 4): CTA covers 128 columns of one graph over all 512 rows
__global__ void __launch_bounds__(128) k_colsum() {
    __shared__ float sm_m[NG];
    __shared__ float sm_zi[NG];
    int g = blockIdx.x, jt = blockIdx.y, tid = threadIdx.x;
    for (int i = tid; i < NG; i += 128) {
        sm_m[i]  = g_rowm[g * NG + i];
        sm_zi[i] = g_rowz[g * NG + i];
    }
    __syncthreads();
    int j = jt * 128 + tid;
    const float* Sg = g_scores + (size_t)g * NG * NG;
    float w = 0.f;
#pragma unroll 4
    for (int i = 0; i < NG; i++)
        w += __expf(Sg[(size_t)i * NG + j] - sm_m[i]) * sm_zi[i];
    g_w[g * NG + j] = w;
}

// ---------------- pooled + MLP head ----------------
__global__ void __launch_bounds__(128) k_pooled_head(const float* __restrict__ Wh1,
                                                     const float* __restrict__ bh1,
                                                     const float* __restrict__ Wh2,
                                                     const float* __restrict__ bh2,
                                                     float* __restrict__ out) {
    int g = blockIdx.x, d = threadIdx.x;
    __shared__ float ws[NG];
    __shared__ float pooled[HH];
    __shared__ float hid[64];
    for (int i = d; i < NG; i += 128) ws[i] = g_w[g * NG + i];
    __syncthreads();
    const float* vg = (const float*)g_hs + (size_t)g * NG * HH;
    float acc = 0.f;
    for (int j = 0; j < NG; j++) acc += ws[j] * vg[j * HH + d];
    pooled[d] = acc * (1.0f / (float)NG);
    __syncthreads();
    if (d < 64) {
        float h = bh1[d];
#pragma unroll 8
        for (int k = 0; k < HH; k++) h += pooled[k] * Wh1[k * 64 + d];
        hid[d] = fmaxf(h, 0.f);
    }
    __syncthreads();
    if (d == 0) {
        float o = bh2[0];
#pragma unroll 8
        for (int h = 0; h < 64; h++) o += hid[h] * Wh2[h];
        out[g] = o;
    }
}

// ---------------- launch ----------------
extern "C" void kernel_launch(void* const* d_in, const int* in_sizes, int n_in,
                              void* d_out, int out_size) {
    const float* x   = (const float*)d_in[0];
    const void*  ei  = d_in[1];
    const float* W1  = (const float*)d_in[3];
    const float* b1  = (const float*)d_in[4];
    const float* W2  = (const float*)d_in[5];
    const float* b2  = (const float*)d_in[6];
    const float* Wq  = (const float*)d_in[7];
    const float* bq  = (const float*)d_in[8];
    const float* Wk  = (const float*)d_in[9];
    const float* bk  = (const float*)d_in[10];
    const float* Wv  = (const float*)d_in[11];
    const float* bv  = (const float*)d_in[12];
    const float* Wh1 = (const float*)d_in[13];
    const float* bh1 = (const float*)d_in[14];
    const float* Wh2 = (const float*)d_in[15];
    const float* bh2 = (const float*)d_in[16];
    float* out = (float*)d_out;

    cudaFuncSetAttribute(k_tgemm,   cudaFuncAttributeMaxDynamicSharedMemorySize, DSMEM);
    cudaFuncSetAttribute(k_tscores, cudaFuncAttributeMaxDynamicSharedMemorySize, DSMEM);

    k_dtype_zero<<<NN / 256, 256>>>(ei);                     // #1
    k_hist<<<EE / 256, 256>>>(ei);                           // #2
    k_split<<<261, 256>>>(x, W1, W2, Wq, Wk, Wv);            // #3
    k_tgemm<<<NN / 128, 256, DSMEM>>>(nullptr, nullptr, nullptr, 0);  // #4 conv1 (profiled)
    k_scan1<<<NN / 256, 256>>>();                            // #5
    k_scan2<<<1, 128>>>();                                   // #6
    k_scan3<<<NN / 256, 256>>>();                            // #7
    k_fill<<<EE / 256, 256>>>(ei);                           // #8

    k_aggregate<<<NN * 32 / 256, 256>>>(b1);
    k_tgemm<<<NN / 128, 256, DSMEM>>>(nullptr, nullptr, nullptr, 1);  // conv2
    k_aggregate<<<NN * 32 / 256, 256>>>(b2);

    dim3 qkv(NN / 128, 3);
    k_tgemm<<<qkv, 256, DSMEM>>>(bq, bk, bv, 2);             // fused QKV

    dim3 sg(NG / 128, NG / 128, GG);
    k_tscores<<<sg, 256, DSMEM>>>();
    k_rowstats<<<GG * NG * 32 / 256, 256>>>();
    dim3 cs(GG, NG / 128);
    k_colsum<<<cs, 128>>>();
    k_pooled_head<<<GG, HH>>>(Wh1, bh1, Wh2, bh2, out);
}

// round 14
// speedup vs baseline: 1.3269x; 1.1669x over previous
#include <cuda_runtime.h>
#include <cuda_bf16.h>
#include <cstdint>
#include <cstddef>

#define NN 32768
#define EE 524288
#define HH 128
#define GG 64
#define NG 512   // nodes per graph

// ---------------- device scratch (static, no allocations) ----------------
__device__ int      g_ei64;
__device__ int      g_cnt[NN];
__device__ int      g_off[NN + 1];
__device__ int      g_cur[NN];
__device__ int      g_bsum[128];
__device__ int      g_boff[128];
__device__ int      g_srcs[EE];
__device__ float    g_dinv[NN];
__device__ float4   g_hs[NN * 32];                 // fp32 messages; later reused for V
__device__ uint32_t g_h_hi[NN * 64];               // h split-bf16 (2 elems per uint32)
__device__ uint32_t g_h_lo[NN * 64];
__device__ uint32_t g_q_hi[NN * 64];               // also holds split x before QKV
__device__ uint32_t g_q_lo[NN * 64];
__device__ uint32_t g_k_hi[NN * 64];
__device__ uint32_t g_k_lo[NN * 64];
__device__ uint32_t g_wt_hi[5 * 128 * 64];         // 5 weights, transposed [n][k] split-bf16
__device__ uint32_t g_wt_lo[5 * 128 * 64];
__device__ float    g_scores[(size_t)GG * NG * NG]; // 64 MB scaled scores
__device__ float    g_rowm[GG * NG];
__device__ float    g_rowz[GG * NG];
__device__ float    g_w[GG * NG];

// ---------------- mma.sync / ldmatrix / cp.async helpers ----------------
#define MMA_BF16(D, a0, a1, a2, a3, b0, b1)                                   \
    asm volatile(                                                             \
        "mma.sync.aligned.m16n8k16.row.col.f32.bf16.bf16.f32 "                \
        "{%0,%1,%2,%3}, {%4,%5,%6,%7}, {%8,%9}, {%0,%1,%2,%3};"               \
        : "+f"((D)[0]), "+f"((D)[1]), "+f"((D)[2]), "+f"((D)[3])              \
        : "r"(a0), "r"(a1), "r"(a2), "r"(a3), "r"(b0), "r"(b1))

#define LDSM4(r0, r1, r2, r3, addr)                                           \
    asm volatile("ldmatrix.sync.aligned.m8n8.x4.shared.b16 {%0,%1,%2,%3}, [%4];" \
                 : "=r"(r0), "=r"(r1), "=r"(r2), "=r"(r3) : "r"(addr))

#define LDSM2(r0, r1, addr)                                                   \
    asm volatile("ldmatrix.sync.aligned.m8n8.x2.shared.b16 {%0,%1}, [%2];"    \
                 : "=r"(r0), "=r"(r1) : "r"(addr))

__device__ __forceinline__ void cp16(uint32_t dst, const void* src) {
    asm volatile("cp.async.ca.shared.global [%0], [%1], 16;" :: "r"(dst), "l"(src));
}
#define CP_COMMIT() asm volatile("cp.async.commit_group;" ::: "memory")
#define CP_WAIT(n)  asm volatile("cp.async.wait_group %0;" :: "n"(n) : "memory")

#define PADB 80            // 32 bf16 per row padded to 80 B (bank-disjoint ldmatrix)
#define TILE_B (128 * PADB)     // 10240 B per tile
#define STAGE_B (4 * TILE_B)    // 40960 B per pipeline stage
#define DSMEM (2 * STAGE_B)     // 81920 B dynamic smem

__device__ __forceinline__ uint32_t pack_hi(float a, float b) {
    __nv_bfloat162 h = __halves2bfloat162(__float2bfloat16(a), __float2bfloat16(b));
    return *(uint32_t*)&h;
}
__device__ __forceinline__ uint32_t pack_lo(float a, float b) {
    __nv_bfloat16 ha = __float2bfloat16(a), hb = __float2bfloat16(b);
    __nv_bfloat162 l = __floats2bfloat162_rn(a - __bfloat162float(ha),
                                             b - __bfloat162float(hb));
    return *(uint32_t*)&l;
}

// ---------------- edge index accessors ----------------
__device__ __forceinline__ int edge_src(const void* ei, int e) {
    int v = g_ei64 ? (int)((const long long*)ei)[e] : ((const int*)ei)[e];
    return v & (NN - 1);
}
__device__ __forceinline__ int edge_dst(const void* ei, int e) {
    int v = g_ei64 ? (int)((const long long*)ei)[EE + e] : ((const int*)ei)[EE + e];
    return v & (NN - 1);
}

__global__ void __launch_bounds__(256) k_dtype_zero(const void* ei) {
    int i = blockIdx.x * 256 + threadIdx.x;
    g_cnt[i] = 0;
    if (blockIdx.x == 0) {
        __shared__ int s_ok;
        if (threadIdx.x == 0) s_ok = 1;
        __syncthreads();
        const long long* p = (const long long*)ei;
        int bad = 0;
#pragma unroll
        for (int k = 0; k < 4; k++) {
            long long v = p[threadIdx.x * 4 + k];
            if (v < 0 || v >= NN) bad = 1;
        }
        if (bad) atomicExch(&s_ok, 0);
        __syncthreads();
        if (threadIdx.x == 0) g_ei64 = s_ok;
    }
}

__global__ void k_hist(const void* __restrict__ ei) {
    int e = blockIdx.x * blockDim.x + threadIdx.x;
    if (e < EE) atomicAdd(&g_cnt[edge_dst(ei, e)], 1);
}
__global__ void __launch_bounds__(256) k_scan1() {
    __shared__ int sh[256];
    int t = threadIdx.x;
    int i = blockIdx.x * 256 + t;
    int c = g_cnt[i];
    sh[t] = c;
    __syncthreads();
#pragma unroll
    for (int o = 1; o < 256; o <<= 1) {
        int v = (t >= o) ? sh[t - o] : 0;
        __syncthreads();
        sh[t] += v;
        __syncthreads();
    }
    g_off[i] = sh[t] - c;
    if (t == 255) g_bsum[blockIdx.x] = sh[255];
}
__global__ void __launch_bounds__(128) k_scan2() {
    __shared__ int sh[128];
    int t = threadIdx.x;
    int c = g_bsum[t];
    sh[t] = c;
    __syncthreads();
#pragma unroll
    for (int o = 1; o < 128; o <<= 1) {
        int v = (t >= o) ? sh[t - o] : 0;
        __syncthreads();
        sh[t] += v;
        __syncthreads();
    }
    g_boff[t] = sh[t] - c;
}
__global__ void __launch_bounds__(256) k_scan3() {
    int i = blockIdx.x * 256 + threadIdx.x;
    int off = g_off[i] + g_boff[i >> 8];
    g_off[i] = off;
    g_cur[i] = off;
    g_dinv[i] = rsqrtf((float)g_cnt[i] + 1.0f);
    if (i == 0) g_off[NN] = EE;
}
__global__ void k_fill(const void* __restrict__ ei) {
    int e = blockIdx.x * blockDim.x + threadIdx.x;
    if (e >= EE) return;
    int s = edge_src(ei, e);
    int d = edge_dst(ei, e);
    int slot = atomicAdd(&g_cur[d], 1);
    g_srcs[slot] = s;
}

// ---------------- pre-split: x -> g_q (split), weights -> g_wt transposed split ----------------
__global__ void __launch_bounds__(256) k_split(const float* __restrict__ x,
                                               const float* __restrict__ W1,
                                               const float* __restrict__ W2,
                                               const float* __restrict__ Wq,
                                               const float* __restrict__ Wk,
                                               const float* __restrict__ Wv) {
    int bx = blockIdx.x, tid = threadIdx.x;
    if (bx < 256) {
        size_t m0 = (size_t)bx * 128;
        const float4* X4 = (const float4*)(x + m0 * 128);
#pragma unroll
        for (int it = 0; it < 16; it++) {
            int idx = it * 256 + tid;
            int row = idx >> 5, c4 = idx & 31;
            float4 v = X4[idx];
            size_t o = (m0 + row) * 64 + c4 * 2;
            g_q_hi[o]     = pack_hi(v.x, v.y);
            g_q_hi[o + 1] = pack_hi(v.z, v.w);
            g_q_lo[o]     = pack_lo(v.x, v.y);
            g_q_lo[o + 1] = pack_lo(v.z, v.w);
        }
    } else {
        int w = bx - 256;  // 0..4
        const float* W = (w == 0) ? W1 : (w == 1) ? W2 : (w == 2) ? Wq : (w == 3) ? Wk : Wv;
        const float4* W4 = (const float4*)W;
        uint32_t* Hi = g_wt_hi + w * 8192;
        uint32_t* Lo = g_wt_lo + w * 8192;
#pragma unroll
        for (int it = 0; it < 8; it++) {
            int item = it * 256 + tid;
            int k2 = item >> 5, n4 = item & 31;
            float4 va = W4[(2 * k2) * 32 + n4];
            float4 vb = W4[(2 * k2 + 1) * 32 + n4];
            float aa[4] = {va.x, va.y, va.z, va.w};
            float bb[4] = {vb.x, vb.y, vb.z, vb.w};
#pragma unroll
            for (int j = 0; j < 4; j++) {
                int n = n4 * 4 + j;
                Hi[n * 64 + k2] = pack_hi(aa[j], bb[j]);
                Lo[n * 64 + k2] = pack_lo(aa[j], bb[j]);
            }
        }
    }
}

// ---------------- GEMM core: 128x128 tile, ldmatrix + split-3 MMA over one 32-K chunk ----------------
__device__ __forceinline__ void mma_chunk(float d[4][4][4], uint32_t base,
                                          int wm, int wn, int lane) {
    uint32_t aHi = base, aLo = base + TILE_B;
    uint32_t bHi = base + 2 * TILE_B, bLo = base + 3 * TILE_B;
    uint32_t aOff = (uint32_t)((wm * 64 + (lane & 15)) * PADB + (lane >> 4) * 16);
    uint32_t bOff = (uint32_t)((wn * 32 + (lane & 7)) * PADB + ((lane >> 3) & 1) * 16);
#pragma unroll
    for (int ks = 0; ks < 2; ks++) {
        uint32_t bh[4][2], bl[4][2];
#pragma unroll
        for (int nt = 0; nt < 4; nt++) {
            LDSM2(bh[nt][0], bh[nt][1], bHi + bOff + nt * 8 * PADB + ks * 32);
            LDSM2(bl[nt][0], bl[nt][1], bLo + bOff + nt * 8 * PADB + ks * 32);
        }
#pragma unroll
        for (int mt = 0; mt < 4; mt++) {
            uint32_t ah0, ah1, ah2, ah3, al0, al1, al2, al3;
            LDSM4(ah0, ah1, ah2, ah3, aHi + aOff + mt * 16 * PADB + ks * 32);
            LDSM4(al0, al1, al2, al3, aLo + aOff + mt * 16 * PADB + ks * 32);
#pragma unroll
            for (int nt = 0; nt < 4; nt++) {
                MMA_BF16(d[mt][nt], ah0, ah1, ah2, ah3, bh[nt][0], bh[nt][1]);
                MMA_BF16(d[mt][nt], ah0, ah1, ah2, ah3, bl[nt][0], bl[nt][1]);
                MMA_BF16(d[mt][nt], al0, al1, al2, al3, bh[nt][0], bh[nt][1]);
            }
        }
    }
}

// load one 32-K chunk (4 x 128-row tiles) via cp.async; global rows are 16 uint4 wide
__device__ __forceinline__ void load_chunk(uint32_t base,
                                           const uint4* Ah, const uint4* Al, size_t aRow0,
                                           const uint4* Bh, const uint4* Bl, size_t bRow0,
                                           int kc, int tid) {
#pragma unroll
    for (int it = 0; it < 2; it++) {
        int idx = it * 256 + tid;
        int row = idx >> 2, q = idx & 3;
        uint32_t doff = (uint32_t)(row * PADB + q * 16);
        size_t ga = (aRow0 + row) * 16 + kc * 4 + q;
        size_t gb = (bRow0 + row) * 16 + kc * 4 + q;
        cp16(base + doff,              Ah + ga);
        cp16(base + TILE_B + doff,     Al + ga);
        cp16(base + 2 * TILE_B + doff, Bh + gb);
        cp16(base + 3 * TILE_B + doff, Bl + gb);
    }
}

// epilogue: fp32 -> g_hs (dstMode 0), split-bf16 -> q (1) / k (2)
__device__ __forceinline__ void gemm_epilogue(float d[4][4][4], const float* bias,
                                              int dstMode, size_t m0,
                                              int wm, int wn, int gid, int tig) {
    float* C = (float*)g_hs;
    uint32_t* Hq = (dstMode == 1) ? g_q_hi : g_k_hi;
    uint32_t* Lq = (dstMode == 1) ? g_q_lo : g_k_lo;
#pragma unroll
    for (int mt = 0; mt < 4; mt++) {
        size_t row0 = m0 + wm * 64 + mt * 16 + gid;
        size_t row1 = row0 + 8;
#pragma unroll
        for (int nt = 0; nt < 4; nt++) {
            int col = wn * 32 + nt * 8 + tig * 2;
            float bx = 0.f, by = 0.f;
            if (bias) { bx = bias[col]; by = bias[col + 1]; }
            float v00 = d[mt][nt][0] + bx, v01 = d[mt][nt][1] + by;
            float v10 = d[mt][nt][2] + bx, v11 = d[mt][nt][3] + by;
            if (dstMode == 0) {
                *(float2*)(C + row0 * 128 + col) = make_float2(v00, v01);
                *(float2*)(C + row1 * 128 + col) = make_float2(v10, v11);
            } else {
                int ci = col >> 1;
                Hq[row0 * 64 + ci] = pack_hi(v00, v01);
                Lq[row0 * 64 + ci] = pack_lo(v00, v01);
                Hq[row1 * 64 + ci] = pack_hi(v10, v11);
                Lq[row1 * 64 + ci] = pack_lo(v10, v11);
            }
        }
    }
}

// ---------------- unified node GEMM: C[128-tile,128] = A @ W ----------------
__global__ void __launch_bounds__(256, 2) k_tgemm(const float* __restrict__ bias0,
                                                  const float* __restrict__ bias1,
                                                  const float* __restrict__ bias2,
                                                  int mode) {
    extern __shared__ __align__(16) uint8_t dsm[];
    int tid = threadIdx.x, wid = tid >> 5, lane = tid & 31;
    int gid = lane >> 2, tig = lane & 3;
    int wm = wid >> 2, wn = wid & 3;
    size_t m0 = (size_t)blockIdx.x * 128;

    const uint32_t *srcHi, *srcLo;
    int widx, dstMode;
    const float* bias = nullptr;
    if (mode == 0)      { srcHi = g_q_hi; srcLo = g_q_lo; widx = 0; dstMode = 0; }
    else if (mode == 1) { srcHi = g_h_hi; srcLo = g_h_lo; widx = 1; dstMode = 0; }
    else {
        int y = blockIdx.y;
        srcHi = g_h_hi; srcLo = g_h_lo; widx = 2 + y;
        dstMode = (y == 0) ? 1 : (y == 1) ? 2 : 0;
        bias = (y == 0) ? bias0 : (y == 1) ? bias1 : bias2;
    }
    const uint4* Ah = (const uint4*)srcHi;
    const uint4* Al = (const uint4*)srcLo;
    const uint4* Bh = (const uint4*)(g_wt_hi + widx * 8192);
    const uint4* Bl = (const uint4*)(g_wt_lo + widx * 8192);
    uint32_t smBase = (uint32_t)__cvta_generic_to_shared(dsm);

    float d[4][4][4];
#pragma unroll
    for (int mt = 0; mt < 4; mt++)
#pragma unroll
        for (int nt = 0; nt < 4; nt++)
#pragma unroll
            for (int c = 0; c < 4; c++) d[mt][nt][c] = 0.f;

    load_chunk(smBase, Ah, Al, m0, Bh, Bl, 0, 0, tid);
    CP_COMMIT();
    for (int kc = 0; kc < 4; kc++) {
        if (kc < 3) {
            load_chunk(smBase + ((kc + 1) & 1) * STAGE_B, Ah, Al, m0, Bh, Bl, 0, kc + 1, tid);
            CP_COMMIT();
            CP_WAIT(1);
        } else {
            CP_WAIT(0);
        }
        __syncthreads();
        mma_chunk(d, smBase + (kc & 1) * STAGE_B, wm, wn, lane);
        __syncthreads();
    }
    gemm_epilogue(d, bias, dstMode, m0, wm, wn, gid, tig);
}

// ---------------- scores: S-tile = Q @ K^T * SCALE ----------------
#define SCALE 0.08838834764831845f

__global__ void __launch_bounds__(256, 2) k_tscores() {
    extern __shared__ __align__(16) uint8_t dsm[];
    int tid = threadIdx.x, wid = tid >> 5, lane = tid & 31;
    int gid = lane >> 2, tig = lane & 3;
    int wm = wid >> 2, wn = wid & 3;
    int g = blockIdx.z, ti = blockIdx.y, tj = blockIdx.x;

    size_t qrow = (size_t)(g * NG + ti * 128);
    size_t krow = (size_t)(g * NG + tj * 128);
    const uint4* Qh = (const uint4*)g_q_hi;
    const uint4* Ql = (const uint4*)g_q_lo;
    const uint4* Kh = (const uint4*)g_k_hi;
    const uint4* Kl = (const uint4*)g_k_lo;
    uint32_t smBase = (uint32_t)__cvta_generic_to_shared(dsm);

    float d[4][4][4];
#pragma unroll
    for (int mt = 0; mt < 4; mt++)
#pragma unroll
        for (int nt = 0; nt < 4; nt++)
#pragma unroll
            for (int c = 0; c < 4; c++) d[mt][nt][c] = 0.f;

    load_chunk(smBase, Qh, Ql, qrow, Kh, Kl, krow, 0, tid);
    CP_COMMIT();
    for (int kc = 0; kc < 4; kc++) {
        if (kc < 3) {
            load_chunk(smBase + ((kc + 1) & 1) * STAGE_B, Qh, Ql, qrow, Kh, Kl, krow, kc + 1, tid);
            CP_COMMIT();
            CP_WAIT(1);
        } else {
            CP_WAIT(0);
        }
        __syncthreads();
        mma_chunk(d, smBase + (kc & 1) * STAGE_B, wm, wn, lane);
        __syncthreads();
    }

    float* Sg = g_scores + (size_t)g * NG * NG;
#pragma unroll
    for (int mt = 0; mt < 4; mt++) {
        int i0 = ti * 128 + wm * 64 + mt * 16 + gid;
        int i1 = i0 + 8;
#pragma unroll
        for (int nt = 0; nt < 4; nt++) {
            int col = tj * 128 + wn * 32 + nt * 8 + tig * 2;
            *(float2*)(Sg + (size_t)i0 * NG + col) =
                make_float2(d[mt][nt][0] * SCALE, d[mt][nt][1] * SCALE);
            *(float2*)(Sg + (size_t)i1 * NG + col) =
                make_float2(d[mt][nt][2] * SCALE, d[mt][nt][3] * SCALE);
        }
    }
}

// ---------------- aggregate (writes h as split-bf16); 4-wide MLP gather ----------------
__global__ void __launch_bounds__(256) k_aggregate(const float* __restrict__ b) {
    int t = blockIdx.x * blockDim.x + threadIdx.x;
    int i = t >> 5;
    if (i >= NN) return;
    int lane = t & 31;

    float di = g_dinv[i];
    float4 self = g_hs[(size_t)i * 32 + lane];
    float4 acc;
    acc.x = di * self.x; acc.y = di * self.y;
    acc.z = di * self.z; acc.w = di * self.w;

    int j = g_off[i];
    int end = g_off[i + 1];
    for (; j + 3 < end; j += 4) {
        int s0 = g_srcs[j], s1 = g_srcs[j + 1], s2 = g_srcs[j + 2], s3 = g_srcs[j + 3];
        float w0 = g_dinv[s0], w1 = g_dinv[s1], w2 = g_dinv[s2], w3 = g_dinv[s3];
        float4 v0 = g_hs[(size_t)s0 * 32 + lane];
        float4 v1 = g_hs[(size_t)s1 * 32 + lane];
        float4 v2 = g_hs[(size_t)s2 * 32 + lane];
        float4 v3 = g_hs[(size_t)s3 * 32 + lane];
        acc.x += w0 * v0.x + w1 * v1.x + w2 * v2.x + w3 * v3.x;
        acc.y += w0 * v0.y + w1 * v1.y + w2 * v2.y + w3 * v3.y;
        acc.z += w0 * v0.z + w1 * v1.z + w2 * v2.z + w3 * v3.z;
        acc.w += w0 * v0.w + w1 * v1.w + w2 * v2.w + w3 * v3.w;
    }
    for (; j < end; j++) {
        int s0 = g_srcs[j];
        float w0 = g_dinv[s0];
        float4 v0 = g_hs[(size_t)s0 * 32 + lane];
        acc.x += w0 * v0.x; acc.y += w0 * v0.y;
        acc.z += w0 * v0.z; acc.w += w0 * v0.w;
    }
    float4 bb = ((const float4*)b)[lane];
    float o0 = fmaxf(acc.x * di + bb.x, 0.f);
    float o1 = fmaxf(acc.y * di + bb.y, 0.f);
    float o2 = fmaxf(acc.z * di + bb.z, 0.f);
    float o3 = fmaxf(acc.w * di + bb.w, 0.f);
    size_t base = (size_t)i * 64 + lane * 2;
    g_h_hi[base]     = pack_hi(o0, o1);
    g_h_hi[base + 1] = pack_hi(o2, o3);
    g_h_lo[base]     = pack_lo(o0, o1);
    g_h_lo[base + 1] = pack_lo(o2, o3);
}

// ---------------- per-row softmax stats; also zero g_w ----------------
__global__ void k_rowstats() {
    int gt = blockIdx.x * blockDim.x + threadIdx.x;
    int row = gt >> 5, lane = gt & 31;
    if (row >= GG * NG) return;
    const float* r = g_scores + (size_t)row * NG;
    float v[16];
    float m = -1e30f;
#pragma unroll
    for (int i = 0; i < 16; i++) { v[i] = r[lane + i * 32]; m = fmaxf(m, v[i]); }
#pragma unroll
    for (int o = 16; o > 0; o >>= 1) m = fmaxf(m, __shfl_xor_sync(0xffffffffu, m, o));
    float z = 0.f;
#pragma unroll
    for (int i = 0; i < 16; i++) z += __expf(v[i] - m);
#pragma unroll
    for (int o = 16; o > 0; o >>= 1) z += __shfl_xor_sync(0xffffffffu, z, o);
    if (lane == 0) { g_rowm[row] = m; g_rowz[row] = 1.0f / z; g_w[row] = 0.f; }
}

// ---------------- column weights: grid (GG, 8), 512 threads, 64 rows/block ----------------
__global__ void __launch_bounds__(512) k_colsum() {
    __shared__ float sm_m[64];
    __shared__ float sm_zi[64];
    int g = blockIdx.x, it = blockIdx.y, j = threadIdx.x;
    if (j < 64) {
        sm_m[j]  = g_rowm[g * NG + it * 64 + j];
        sm_zi[j] = g_rowz[g * NG + it * 64 + j];
    }
    __syncthreads();
    const float* Sg = g_scores + (size_t)g * NG * NG + (size_t)it * 64 * NG;
    float w = 0.f;
#pragma unroll 4
    for (int i = 0; i < 64; i++)
        w += __expf(Sg[(size_t)i * NG + j] - sm_m[i]) * sm_zi[i];
    atomicAdd(&g_w[g * NG + j], w);
}

// ---------------- pooled + MLP head ----------------
__global__ void __launch_bounds__(128) k_pooled_head(const float* __restrict__ Wh1,
                                                     const float* __restrict__ bh1,
                                                     const float* __restrict__ Wh2,
                                                     const float* __restrict__ bh2,
                                                     float* __restrict__ out) {
    int g = blockIdx.x, d = threadIdx.x;
    __shared__ float ws[NG];
    __shared__ float pooled[HH];
    __shared__ float hid[64];
    for (int i = d; i < NG; i += 128) ws[i] = g_w[g * NG + i];
    __syncthreads();
    const float* vg = (const float*)g_hs + (size_t)g * NG * HH;
    float acc = 0.f;
    for (int j = 0; j < NG; j++) acc += ws[j] * vg[j * HH + d];
    pooled[d] = acc * (1.0f / (float)NG);
    __syncthreads();
    if (d < 64) {
        float h = bh1[d];
#pragma unroll 8
        for (int k = 0; k < HH; k++) h += pooled[k] * Wh1[k * 64 + d];
        hid[d] = fmaxf(h, 0.f);
    }
    __syncthreads();
    if (d == 0) {
        float o = bh2[0];
#pragma unroll 8
        for (int h = 0; h < 64; h++) o += hid[h] * Wh2[h];
        out[g] = o;
    }
}

// ---------------- launch ----------------
extern "C" void kernel_launch(void* const* d_in, const int* in_sizes, int n_in,
                              void* d_out, int out_size) {
    const float* x   = (const float*)d_in[0];
    const void*  ei  = d_in[1];
    const float* W1  = (const float*)d_in[3];
    const float* b1  = (const float*)d_in[4];
    const float* W2  = (const float*)d_in[5];
    const float* b2  = (const float*)d_in[6];
    const float* Wq  = (const float*)d_in[7];
    const float* bq  = (const float*)d_in[8];
    const float* Wk  = (const float*)d_in[9];
    const float* bk  = (const float*)d_in[10];
    const float* Wv  = (const float*)d_in[11];
    const float* bv  = (const float*)d_in[12];
    const float* Wh1 = (const float*)d_in[13];
    const float* bh1 = (const float*)d_in[14];
    const float* Wh2 = (const float*)d_in[15];
    const float* bh2 = (const float*)d_in[16];
    float* out = (float*)d_out;

    cudaFuncSetAttribute(k_tgemm,   cudaFuncAttributeMaxDynamicSharedMemorySize, DSMEM);
    cudaFuncSetAttribute(k_tscores, cudaFuncAttributeMaxDynamicSharedMemorySize, DSMEM);

    k_dtype_zero<<<NN / 256, 256>>>(ei);                     // #1
    k_hist<<<EE / 256, 256>>>(ei);                           // #2
    k_split<<<261, 256>>>(x, W1, W2, Wq, Wk, Wv);            // #3
    k_tgemm<<<NN / 128, 256, DSMEM>>>(nullptr, nullptr, nullptr, 0);  // #4 conv1 (profiled)
    k_scan1<<<NN / 256, 256>>>();                            // #5
    k_scan2<<<1, 128>>>();                                   // #6
    k_scan3<<<NN / 256, 256>>>();                            // #7
    k_fill<<<EE / 256, 256>>>(ei);                           // #8

    k_aggregate<<<NN * 32 / 256, 256>>>(b1);
    k_tgemm<<<NN / 128, 256, DSMEM>>>(nullptr, nullptr, nullptr, 1);  // conv2
    k_aggregate<<<NN * 32 / 256, 256>>>(b2);

    dim3 qkv(NN / 128, 3);
    k_tgemm<<<qkv, 256, DSMEM>>>(bq, bk, bv, 2);             // fused QKV

    dim3 sg(NG / 128, NG / 128, GG);
    k_tscores<<<sg, 256, DSMEM>>>();
    k_rowstats<<<GG * NG * 32 / 256, 256>>>();
    dim3 cs(GG, NG / 64);                                    // (64, 8)
    k_colsum<<<cs, 512>>>();
    k_pooled_head<<<GG, HH>>>(Wh1, bh1, Wh2, bh2, out);
}